// round 2
// baseline (speedup 1.0000x reference)
#include <cuda_runtime.h>

// BilinearInteractionLayer: out[b, p, e] = (x[b,i(p)] @ W)[e] * x[b,j(p)][e]
// B=8192, F=32, E=64, P=496 (upper-triangular field pairs, i<j)
// HBM-store-bound: ~1.04 GB output. One CTA per batch row.

constexpr int F = 32;
constexpr int E = 64;
constexpr int P = 496;        // F*(F-1)/2
constexpr int THREADS = 256;

__global__ __launch_bounds__(THREADS) void bilinear_kernel(
    const float* __restrict__ x,     // [B, F, E]
    const float* __restrict__ W,     // [E, E]
    float* __restrict__ out)         // [B, P, E]
{
    __shared__ float xs [F * E];     // 8 KB  raw x[b]
    __shared__ float xws[F * E];     // 8 KB  x[b] @ W
    __shared__ float Ws [E * E];     // 16 KB W
    __shared__ int   pij[P];         // packed (i*16)<<16 | (j*16) float4 offsets

    const int tid = threadIdx.x;
    const int b   = blockIdx.x;

    // ---- Stage x[b] and W into smem (vectorized, coalesced) ----
    {
        const float4* xg  = reinterpret_cast<const float4*>(x + (size_t)b * F * E);
        float4*       xs4 = reinterpret_cast<float4*>(xs);
        #pragma unroll
        for (int i = 0; i < (F * E / 4) / THREADS; i++)       // 2 iters
            xs4[tid + i * THREADS] = xg[tid + i * THREADS];

        const float4* wg  = reinterpret_cast<const float4*>(W);
        float4*       ws4 = reinterpret_cast<float4*>(Ws);
        #pragma unroll
        for (int i = 0; i < (E * E / 4) / THREADS; i++)       // 4 iters
            ws4[tid + i * THREADS] = wg[tid + i * THREADS];
    }

    // ---- Pair-index table: triu_indices(F, k=1) ordering ----
    // NOTE: P (496) > THREADS (256) -> must stride, not a single if.
    for (int p = tid; p < P; p += THREADS) {
        int i = 0, start = 0;
        while (start + (F - 1 - i) <= p) { start += (F - 1 - i); i++; }
        int j = i + 1 + (p - start);
        pij[p] = ((i * (E / 4)) << 16) | (j * (E / 4));       // float4 row offsets
    }
    __syncthreads();

    // ---- GEMM: xw[r][c] = sum_k xs[r][k] * W[k][c] ----
    // Thread owns 2 rows x 4 cols. 256 threads cover 32x64.
    {
        const int c4 = tid & 15;          // column group (4 floats)
        const int r0 = tid >> 4;          // rows r0 and r0+16
        float4 acc0 = {0.f, 0.f, 0.f, 0.f};
        float4 acc1 = {0.f, 0.f, 0.f, 0.f};
        const float4* Wv = reinterpret_cast<const float4*>(Ws);
        #pragma unroll 8
        for (int k = 0; k < E; k++) {
            const float  a0 = xs[r0 * E + k];
            const float  a1 = xs[(r0 + 16) * E + k];
            const float4 w  = Wv[k * 16 + c4];
            acc0.x += a0 * w.x; acc0.y += a0 * w.y;
            acc0.z += a0 * w.z; acc0.w += a0 * w.w;
            acc1.x += a1 * w.x; acc1.y += a1 * w.y;
            acc1.z += a1 * w.z; acc1.w += a1 * w.w;
        }
        float4* xwv = reinterpret_cast<float4*>(xws);
        xwv[r0 * 16 + c4]        = acc0;
        xwv[(r0 + 16) * 16 + c4] = acc1;
    }
    __syncthreads();

    // ---- Stream out: out[b, p, :] = xw[i(p)] * x[j(p)], float4 coalesced ----
    {
        const float4* xwv = reinterpret_cast<const float4*>(xws);
        const float4* xv  = reinterpret_cast<const float4*>(xs);
        float4* og = reinterpret_cast<float4*>(out + (size_t)b * P * E);
        #pragma unroll 4
        for (int idx = tid; idx < P * (E / 4); idx += THREADS) {   // 31 iters
            const int pr = pij[idx >> 4];
            const int q  = idx & 15;
            const float4 a = xwv[(pr >> 16) + q];
            const float4 c = xv [(pr & 0xffff) + q];
            float4 r;
            r.x = a.x * c.x; r.y = a.y * c.y;
            r.z = a.z * c.z; r.w = a.w * c.w;
            og[idx] = r;
        }
    }
}

extern "C" void kernel_launch(void* const* d_in, const int* in_sizes, int n_in,
                              void* d_out, int out_size)
{
    // Robust input-order detection: W has exactly E*E elements, x is much larger.
    const float* x;
    const float* W;
    int x_elems;
    if (n_in >= 2 && in_sizes[0] > in_sizes[1]) {
        x = (const float*)d_in[0]; W = (const float*)d_in[1]; x_elems = in_sizes[0];
    } else {
        x = (const float*)d_in[1]; W = (const float*)d_in[0]; x_elems = in_sizes[1];
    }

    float* out = (float*)d_out;               // [B, P, E]
    const int B = x_elems / (F * E);          // 8192
    bilinear_kernel<<<B, THREADS>>>(x, W, out);
}

// round 6
// speedup vs baseline: 1.1778x; 1.1778x over previous
#include <cuda_runtime.h>

// BilinearInteractionLayer: out[b, p, e] = (x[b,i(p)] @ W)[e] * x[b,j(p)][e]
// B=8192, F=32, E=64, P=496. HBM-store-bound target (~1.04 GB out).
// One CTA per batch row. L1-wavefront-minimized design:
//   - GEMM: 128 threads, 4 rows x 4 cols each (halves W smem traffic)
//   - Store: run-structured, xw[i] register-cached per run (1 LDS + 1 STG per float4)

constexpr int F = 32;
constexpr int E = 64;
constexpr int P = 496;
constexpr int THREADS = 256;

__global__ __launch_bounds__(THREADS) void bilinear_kernel(
    const float* __restrict__ x,     // [B, F, E]
    const float* __restrict__ W,     // [E, E]
    float* __restrict__ out)         // [B, P, E]
{
    __shared__ float xs [F * E];     // 8 KB  raw x[b]
    __shared__ float xws[F * E];     // 8 KB  x[b] @ W
    __shared__ float Ws [E * E];     // 16 KB W

    const int tid = threadIdx.x;
    const int b   = blockIdx.x;

    // ---- Stage x[b] and W into smem (vectorized, coalesced) ----
    {
        const float4* xg  = reinterpret_cast<const float4*>(x + (size_t)b * F * E);
        float4*       xs4 = reinterpret_cast<float4*>(xs);
        #pragma unroll
        for (int i = 0; i < (F * E / 4) / THREADS; i++)       // 2 iters
            xs4[tid + i * THREADS] = xg[tid + i * THREADS];

        const float4* wg  = reinterpret_cast<const float4*>(W);
        float4*       ws4 = reinterpret_cast<float4*>(Ws);
        #pragma unroll
        for (int i = 0; i < (E * E / 4) / THREADS; i++)       // 4 iters
            ws4[tid + i * THREADS] = wg[tid + i * THREADS];
    }
    __syncthreads();

    // ---- GEMM: xw = xs @ W. 128 threads, each 4 rows x 4 cols. ----
    // Thread (q = t&15, w = t>>4): rows {w, w+8, w+16, w+24}, cols 4q..4q+3.
    if (tid < 128) {
        const int q = tid & 15;
        const int w = tid >> 4;          // 0..7
        float4 acc0 = {0.f,0.f,0.f,0.f};
        float4 acc1 = {0.f,0.f,0.f,0.f};
        float4 acc2 = {0.f,0.f,0.f,0.f};
        float4 acc3 = {0.f,0.f,0.f,0.f};
        const float4* Wv = reinterpret_cast<const float4*>(Ws);
        #pragma unroll 4
        for (int k = 0; k < E; k++) {
            const float4 wv = Wv[k * 16 + q];
            const float a0 = xs[(w     ) * E + k];
            const float a1 = xs[(w +  8) * E + k];
            const float a2 = xs[(w + 16) * E + k];
            const float a3 = xs[(w + 24) * E + k];
            acc0.x += a0*wv.x; acc0.y += a0*wv.y; acc0.z += a0*wv.z; acc0.w += a0*wv.w;
            acc1.x += a1*wv.x; acc1.y += a1*wv.y; acc1.z += a1*wv.z; acc1.w += a1*wv.w;
            acc2.x += a2*wv.x; acc2.y += a2*wv.y; acc2.z += a2*wv.z; acc2.w += a2*wv.w;
            acc3.x += a3*wv.x; acc3.y += a3*wv.y; acc3.z += a3*wv.z; acc3.w += a3*wv.w;
        }
        float4* xwv = reinterpret_cast<float4*>(xws);
        xwv[(w     ) * 16 + q] = acc0;
        xwv[(w +  8) * 16 + q] = acc1;
        xwv[(w + 16) * 16 + q] = acc2;
        xwv[(w + 24) * 16 + q] = acc3;
    }
    __syncthreads();

    // ---- Store phase: run-structured. Worker w2 owns runs i=w2 and i=30-w2. ----
    // Run i covers rows p0(i)..p0(i)+(30-i), j = i+1..31, p0(i) = 31i - i(i-1)/2.
    // a = xw[i] is loaded ONCE per run into registers; per row: 1 LDS.128 + 1 STG.128.
    {
        const int q  = tid & 15;
        const int w2 = tid >> 4;         // 0..15
        const float4* xwv = reinterpret_cast<const float4*>(xws);
        const float4* xv  = reinterpret_cast<const float4*>(xs);
        float4* og = reinterpret_cast<float4*>(out + (size_t)b * P * E) + q;

        // Run 1: i = w2 (length 31 - w2)
        {
            const int i = w2;
            const float4 a = xwv[i * 16 + q];
            float4* dst = og + (size_t)(i * 31 - i * (i - 1) / 2) * 16;
            #pragma unroll 4
            for (int j = i + 1; j < F; j++, dst += 16) {
                const float4 c = xv[j * 16 + q];
                float4 r;
                r.x = a.x*c.x; r.y = a.y*c.y; r.z = a.z*c.z; r.w = a.w*c.w;
                *dst = r;
            }
        }
        // Run 2: i = 30 - w2 (length 1 + w2); skip for w2 == 15 (duplicate of run 1)
        if (w2 < 15) {
            const int i = 30 - w2;
            const float4 a = xwv[i * 16 + q];
            float4* dst = og + (size_t)(i * 31 - i * (i - 1) / 2) * 16;
            #pragma unroll 4
            for (int j = i + 1; j < F; j++, dst += 16) {
                const float4 c = xv[j * 16 + q];
                float4 r;
                r.x = a.x*c.x; r.y = a.y*c.y; r.z = a.z*c.z; r.w = a.w*c.w;
                *dst = r;
            }
        }
    }
}

extern "C" void kernel_launch(void* const* d_in, const int* in_sizes, int n_in,
                              void* d_out, int out_size)
{
    // Robust input-order detection: W has exactly E*E elements, x is much larger.
    const float* x;
    const float* W;
    int x_elems;
    if (n_in >= 2 && in_sizes[0] > in_sizes[1]) {
        x = (const float*)d_in[0]; W = (const float*)d_in[1]; x_elems = in_sizes[0];
    } else {
        x = (const float*)d_in[1]; W = (const float*)d_in[0]; x_elems = in_sizes[1];
    }

    float* out = (float*)d_out;               // [B, P, E]
    const int B = x_elems / (F * E);          // 8192
    bilinear_kernel<<<B, THREADS>>>(x, W, out);
}